// round 3
// baseline (speedup 1.0000x reference)
#include <cuda_runtime.h>
#include <math.h>

#define NN 50000
#define EE 800000
#define DIN 128
#define DD 64
#define GG 512
#define SCALING_F 0.46211715726000974f

// ---------------- scratch (static device globals; no allocation) ----------------
__device__ float g_x[NN * DD];
__device__ float g_h[NN * DD];
__device__ float g_agg[NN * DD];
__device__ float g_Z[3][NN * DD];
__device__ float g_stats[2 * DD];   // [0:64) sum, [64:128) sumsq of h columns
__device__ float g_pool[GG * DD];

__device__ __forceinline__ float warp_sum(float v) {
#pragma unroll
    for (int o = 16; o; o >>= 1) v += __shfl_xor_sync(0xffffffffu, v, o);
    return v;
}

// ---------------- zero kernels ----------------
__global__ void k_zero_agg_stats() {
    int t = blockIdx.x * blockDim.x + threadIdx.x;
    if (t < NN * DD) g_agg[t] = 0.f;
    if (t < 2 * DD) g_stats[t] = 0.f;
}
__global__ void k_zero_pool() {
    int t = blockIdx.x * blockDim.x + threadIdx.x;
    if (t < GG * DD) g_pool[t] = 0.f;
}

// ---------------- GEMM 0: x1 = relu(x[N,128] @ W0[128,64] + b0) ----------------
__global__ void k_gemm0(const float* __restrict__ xin,
                        const float* __restrict__ W0,
                        const float* __restrict__ b0) {
    __shared__ __align__(16) float xs[64 * 64];
    __shared__ __align__(16) float Ws[64 * 64];
    int t = threadIdx.x;
    int R0 = blockIdx.x * 64;
    int c4 = (t & 15) * 4;
    int rb = (t >> 4) * 4;
    float acc[4][4] = {};
    for (int kb = 0; kb < 128; kb += 64) {
#pragma unroll
        for (int i2 = 0; i2 < 16; i2++) {
            int idx = t + i2 * 256;
            int r = idx >> 6, c = idx & 63;
            int gr = R0 + r;
            xs[idx] = (gr < NN) ? xin[gr * 128 + kb + c] : 0.f;
            Ws[idx] = W0[(kb + r) * 64 + c];
        }
        __syncthreads();
#pragma unroll 8
        for (int k = 0; k < 64; k++) {
            float4 w = *(const float4*)&Ws[k * 64 + c4];
            float xr[4];
#pragma unroll
            for (int r = 0; r < 4; r++) xr[r] = xs[(rb + r) * 64 + k];
#pragma unroll
            for (int r = 0; r < 4; r++) {
                acc[r][0] = fmaf(xr[r], w.x, acc[r][0]);
                acc[r][1] = fmaf(xr[r], w.y, acc[r][1]);
                acc[r][2] = fmaf(xr[r], w.z, acc[r][2]);
                acc[r][3] = fmaf(xr[r], w.w, acc[r][3]);
            }
        }
        __syncthreads();
    }
    float4 bb = *(const float4*)&b0[c4];
#pragma unroll
    for (int r = 0; r < 4; r++) {
        int gr = R0 + rb + r;
        if (gr < NN) {
            float4 o;
            o.x = fmaxf(acc[r][0] + bb.x, 0.f);
            o.y = fmaxf(acc[r][1] + bb.y, 0.f);
            o.z = fmaxf(acc[r][2] + bb.z, 0.f);
            o.w = fmaxf(acc[r][3] + bb.w, 0.f);
            *(float4*)&g_x[gr * 64 + c4] = o;
        }
    }
}

// ---------------- Z1 = SCALING * project(x1) ----------------
__global__ void k_init() {
    int gw = (blockIdx.x * blockDim.x + threadIdx.x) >> 5;
    int lane = threadIdx.x & 31;
    if (gw >= NN) return;
    const float2* x2 = (const float2*)g_x;
    float2 v = x2[gw * 32 + lane];
    float n2 = warp_sum(v.x * v.x + v.y * v.y);
    float cn = fmaxf(sqrtf(n2), 1e-15f);
    float f = (cn > 0.996f) ? (0.996f / cn) : 1.0f;
    f *= SCALING_F;
    float2* z = (float2*)g_Z[0];
    z[gw * 32 + lane] = make_float2(v.x * f, v.y * f);
}

// ---------------- edge scatter: agg[dst] += x[src] ----------------
__global__ void k_edge(const int* __restrict__ ei) {
    unsigned tid = blockIdx.x * 256u + threadIdx.x;
    unsigned e = tid >> 6;
    unsigned d = tid & 63u;
    int s = __ldg(&ei[e]);
    int dn = __ldg(&ei[EE + e]);
    float v = __ldg(&g_x[(unsigned)s * 64u + d]);
    atomicAdd(&g_agg[(unsigned)dn * 64u + d], v);
}

// ---------------- GEMM A: h = relu((x+agg) @ W1 + b1), accumulate BN stats ----------------
__global__ void k_gemmA(const float* __restrict__ W, const float* __restrict__ b) {
    __shared__ __align__(16) float xs[64 * 64];
    __shared__ __align__(16) float Ws[64 * 64];
    __shared__ float s_sum[64], s_sq[64];
    int t = threadIdx.x;
    int R0 = blockIdx.x * 64;
    if (t < 64) { s_sum[t] = 0.f; s_sq[t] = 0.f; }
#pragma unroll
    for (int i2 = 0; i2 < 16; i2++) {
        int idx = t + i2 * 256;
        int r = idx >> 6, c = idx & 63;
        int gr = R0 + r;
        xs[idx] = (gr < NN) ? g_x[gr * 64 + c] + g_agg[gr * 64 + c] : 0.f;
        Ws[idx] = W[idx];
    }
    __syncthreads();
    int c4 = (t & 15) * 4;
    int rb = (t >> 4) * 4;
    float acc[4][4] = {};
#pragma unroll 8
    for (int k = 0; k < 64; k++) {
        float4 w = *(const float4*)&Ws[k * 64 + c4];
        float xr[4];
#pragma unroll
        for (int r = 0; r < 4; r++) xr[r] = xs[(rb + r) * 64 + k];
#pragma unroll
        for (int r = 0; r < 4; r++) {
            acc[r][0] = fmaf(xr[r], w.x, acc[r][0]);
            acc[r][1] = fmaf(xr[r], w.y, acc[r][1]);
            acc[r][2] = fmaf(xr[r], w.z, acc[r][2]);
            acc[r][3] = fmaf(xr[r], w.w, acc[r][3]);
        }
    }
    float4 bb = *(const float4*)&b[c4];
    float ps[4] = {}, pq[4] = {};
#pragma unroll
    for (int r = 0; r < 4; r++) {
        int gr = R0 + rb + r;
        float o[4];
        o[0] = fmaxf(acc[r][0] + bb.x, 0.f);
        o[1] = fmaxf(acc[r][1] + bb.y, 0.f);
        o[2] = fmaxf(acc[r][2] + bb.z, 0.f);
        o[3] = fmaxf(acc[r][3] + bb.w, 0.f);
        if (gr < NN) {
            *(float4*)&g_h[gr * 64 + c4] = make_float4(o[0], o[1], o[2], o[3]);
#pragma unroll
            for (int j = 0; j < 4; j++) { ps[j] += o[j]; pq[j] += o[j] * o[j]; }
        }
    }
#pragma unroll
    for (int j = 0; j < 4; j++) {
        atomicAdd(&s_sum[c4 + j], ps[j]);
        atomicAdd(&s_sq[c4 + j], pq[j]);
    }
    __syncthreads();
    if (t < 64) {
        atomicAdd(&g_stats[t], s_sum[t]);
        atomicAdd(&g_stats[64 + t], s_sq[t]);
    }
}

// ---------------- GEMM B: x = relu(BN(h) @ W2 + b2), x[:,63] = 0 ----------------
__global__ void k_gemmB(const float* __restrict__ W, const float* __restrict__ b,
                        const float* __restrict__ gamma, const float* __restrict__ beta) {
    __shared__ __align__(16) float xs[64 * 64];
    __shared__ __align__(16) float Ws[64 * 64];
    __shared__ float sca[64], shi[64];
    int t = threadIdx.x;
    int R0 = blockIdx.x * 64;
    if (t < 64) {
        float mean = g_stats[t] * (1.0f / NN);
        float var = g_stats[64 + t] * (1.0f / NN) - mean * mean;
        float inv = rsqrtf(var + 1e-5f);
        float s = gamma[t] * inv;
        sca[t] = s;
        shi[t] = beta[t] - mean * s;
    }
    __syncthreads();
#pragma unroll
    for (int i2 = 0; i2 < 16; i2++) {
        int idx = t + i2 * 256;
        int r = idx >> 6, c = idx & 63;
        int gr = R0 + r;
        xs[idx] = (gr < NN) ? g_h[gr * 64 + c] * sca[c] + shi[c] : 0.f;
        Ws[idx] = W[idx];
    }
    __syncthreads();
    int c4 = (t & 15) * 4;
    int rb = (t >> 4) * 4;
    float acc[4][4] = {};
#pragma unroll 8
    for (int k = 0; k < 64; k++) {
        float4 w = *(const float4*)&Ws[k * 64 + c4];
        float xr[4];
#pragma unroll
        for (int r = 0; r < 4; r++) xr[r] = xs[(rb + r) * 64 + k];
#pragma unroll
        for (int r = 0; r < 4; r++) {
            acc[r][0] = fmaf(xr[r], w.x, acc[r][0]);
            acc[r][1] = fmaf(xr[r], w.y, acc[r][1]);
            acc[r][2] = fmaf(xr[r], w.z, acc[r][2]);
            acc[r][3] = fmaf(xr[r], w.w, acc[r][3]);
        }
    }
    float4 bb = *(const float4*)&b[c4];
#pragma unroll
    for (int r = 0; r < 4; r++) {
        int gr = R0 + rb + r;
        if (gr < NN) {
            float o[4];
            o[0] = fmaxf(acc[r][0] + bb.x, 0.f);
            o[1] = fmaxf(acc[r][1] + bb.y, 0.f);
            o[2] = fmaxf(acc[r][2] + bb.z, 0.f);
            o[3] = fmaxf(acc[r][3] + bb.w, 0.f);
            if (c4 + 3 == 63) o[3] = 0.f;   // x[:, -1] = 0
            *(float4*)&g_x[gr * 64 + c4] = make_float4(o[0], o[1], o[2], o[3]);
        }
    }
}

// ---------------- hyperbolic update (warp per node) ----------------
__global__ void k_hyp(int iter, int last, const int* __restrict__ batch) {
    int gw = (blockIdx.x * blockDim.x + threadIdx.x) >> 5;
    int lane = threadIdx.x & 31;
    if (gw >= NN) return;
    int icur = iter;
    int inew = (iter + 1) % 3;
    int ipar = (iter + 2) % 3;
    int off = gw * 32 + lane;

    const float2* x2 = (const float2*)g_x;
    const float2* zc2 = (const float2*)g_Z[icur];
    const float2* zp2 = (const float2*)g_Z[ipar];
    float2* zn2 = (float2*)g_Z[inew];

    float2 xv = x2[off];
    float2 mc = zc2[off];
    float2 pp = (iter == 0) ? make_float2(0.f, 0.f) : zp2[off];

    // z_children = SCALING * project(x)
    float n2 = warp_sum(xv.x * xv.x + xv.y * xv.y);
    float cn = fmaxf(sqrtf(n2), 1e-15f);
    float f = (cn > 0.996f) ? (0.996f / cn) : 1.0f;
    f *= SCALING_F;
    float2 zc = make_float2(xv.x * f, xv.y * f);

    // a = mu / cmin(||mu||^2),  mu = z_current
    float mn2 = fmaxf(warp_sum(mc.x * mc.x + mc.y * mc.y), 1e-15f);
    float2 a = make_float2(mc.x / mn2, mc.y / mn2);
    float a2 = warp_sum(a.x * a.x + a.y * a.y);
    float r2 = a2 - 1.f;

    // z_parent' = isometric_transform(z_parent, a)
    float2 u = make_float2(pp.x - a.x, pp.y - a.y);
    float un2 = fmaxf(warp_sum(u.x * u.x + u.y * u.y), 1e-15f);
    float s1 = r2 / un2;
    float2 zp = make_float2(s1 * u.x + a.x, s1 * u.y + a.y);

    // reflect_through_zero(zp, e_{63}, zc)
    float pn = fmaxf(sqrtf(warp_sum(zp.x * zp.x + zp.y * zp.y)), 1e-15f);
    float2 p_ = make_float2(zp.x / pn, zp.y / pn);
    float2 r = make_float2(-p_.x, -p_.y);
    if (lane == 31) r.y += 1.0f;   // q_ = e63
    float num = warp_sum(r.x * zc.x + r.y * zc.y);
    float den = warp_sum(r.x * r.x + r.y * r.y);
    float m = num / den;
    float2 zcc = make_float2(zc.x - 2.f * r.x * m, zc.y - 2.f * r.y * m);

    // z_all = isometric_transform(zcc, a)
    float2 u2 = make_float2(zcc.x - a.x, zcc.y - a.y);
    float u2n = fmaxf(warp_sum(u2.x * u2.x + u2.y * u2.y), 1e-15f);
    float s2 = r2 / u2n;
    float2 zn = make_float2(s2 * u2.x + a.x, s2 * u2.y + a.y);
    zn2[off] = zn;

    if (last) {
        // xh = logmap0(zn); pool by batch
        float yn = fmaxf(sqrtf(warp_sum(zn.x * zn.x + zn.y * zn.y)), 1e-15f);
        float tt = fminf(yn, 1.0f);   // f32(1 - 1e-15) == 1.0f
        float sc = atanhf(tt) / yn;
        int bg = __ldg(&batch[gw]);
        atomicAdd(&g_pool[bg * 64 + lane * 2], zn.x * sc);
        atomicAdd(&g_pool[bg * 64 + lane * 2 + 1], zn.y * sc);
    }
}

// ---------------- head MLP + log_softmax (block per graph) ----------------
__global__ void k_head(const float* __restrict__ fc1W, const float* __restrict__ fc1b,
                       const float* __restrict__ fc2W, const float* __restrict__ fc2b,
                       const float* __restrict__ fc3W, const float* __restrict__ fc3b,
                       float* __restrict__ out) {
    __shared__ float sp[64], h1[128], h2[64], lo[10];
    int g = blockIdx.x;
    int t = threadIdx.x;
    if (t < 64) sp[t] = g_pool[g * 64 + t];
    __syncthreads();
    {
        float acc = fc1b[t];
#pragma unroll 8
        for (int k = 0; k < 64; k++) acc = fmaf(sp[k], fc1W[k * 128 + t], acc);
        h1[t] = fmaxf(acc, 0.f);
    }
    __syncthreads();
    if (t < 64) {
        float acc = fc2b[t];
#pragma unroll 8
        for (int k = 0; k < 128; k++) acc = fmaf(h1[k], fc2W[k * 64 + t], acc);
        h2[t] = fmaxf(acc, 0.f);
    }
    __syncthreads();
    if (t < 10) {
        float acc = fc3b[t];
#pragma unroll 8
        for (int k = 0; k < 64; k++) acc = fmaf(h2[k], fc3W[k * 10 + t], acc);
        lo[t] = acc;
    }
    __syncthreads();
    if (t == 0) {
        float mx = lo[0];
#pragma unroll
        for (int c = 1; c < 10; c++) mx = fmaxf(mx, lo[c]);
        float s = 0.f;
#pragma unroll
        for (int c = 0; c < 10; c++) s += expf(lo[c] - mx);
        float lse = mx + logf(s);
#pragma unroll
        for (int c = 0; c < 10; c++) out[g * 10 + c] = lo[c] - lse;
    }
}

// ---------------- launch ----------------
extern "C" void kernel_launch(void* const* d_in, const int* in_sizes, int n_in,
                              void* d_out, int out_size) {
    const float* x     = (const float*)d_in[0];
    const int*   ei    = (const int*)d_in[1];
    const int*   batch = (const int*)d_in[2];
    const float* W0    = (const float*)d_in[3];
    const float* b0    = (const float*)d_in[4];
    const float* cW1   = (const float*)d_in[5];
    const float* cb1   = (const float*)d_in[6];
    const float* gamma = (const float*)d_in[7];
    const float* beta  = (const float*)d_in[8];
    const float* cW2   = (const float*)d_in[9];
    const float* cb2   = (const float*)d_in[10];
    const float* fc1W  = (const float*)d_in[11];
    const float* fc1b  = (const float*)d_in[12];
    const float* fc2W  = (const float*)d_in[13];
    const float* fc2b  = (const float*)d_in[14];
    const float* fc3W  = (const float*)d_in[15];
    const float* fc3b  = (const float*)d_in[16];
    float* out = (float*)d_out;

    const int gemmGrid = (NN + 63) / 64;        // 782
    const int warpGrid = (NN * 32 + 255) / 256; // 6250
    const int edgeGrid = (EE * 64) / 256;       // 200000
    const int zeroGrid = (NN * DD + 255) / 256; // 12500

    k_gemm0<<<gemmGrid, 256>>>(x, W0, b0);
    k_init<<<warpGrid, 256>>>();
    k_zero_pool<<<(GG * DD + 255) / 256, 256>>>();

    for (int l = 0; l < 3; l++) {
        k_zero_agg_stats<<<zeroGrid, 256>>>();
        k_edge<<<edgeGrid, 256>>>(ei);
        k_gemmA<<<gemmGrid, 256>>>(cW1 + l * 64 * 64, cb1 + l * 64);
        k_gemmB<<<gemmGrid, 256>>>(cW2 + l * 64 * 64, cb2 + l * 64,
                                   gamma + l * 64, beta + l * 64);
        k_hyp<<<warpGrid, 256>>>(l, (l == 2) ? 1 : 0, batch);
    }
    k_head<<<512, 128>>>(fc1W, fc1b, fc2W, fc2b, fc3W, fc3b, out);
}

// round 4
// speedup vs baseline: 1.3261x; 1.3261x over previous
#include <cuda_runtime.h>
#include <math.h>

#define NN 50000
#define EE 800000
#define DIN 128
#define DD 64
#define GG 512
#define SCALING_F 0.46211715726000974f

// ---------------- scratch (static device globals; no allocation) ----------------
__device__ __align__(16) float g_x[NN * DD];
__device__ __align__(16) float g_h[NN * DD];
__device__ __align__(16) float g_agg[NN * DD];
__device__ __align__(16) float g_Z[3][NN * DD];
__device__ __align__(16) float g_stats[2 * DD];   // [0:64) sum, [64:128) sumsq
__device__ __align__(16) float g_pool[GG * DD];

__device__ __forceinline__ float warp_sum(float v) {
#pragma unroll
    for (int o = 16; o; o >>= 1) v += __shfl_xor_sync(0xffffffffu, v, o);
    return v;
}

__device__ __forceinline__ void red_add_v4(float* p, float4 v) {
    asm volatile("red.global.add.v4.f32 [%0], {%1, %2, %3, %4};"
                 :: "l"(p), "f"(v.x), "f"(v.y), "f"(v.z), "f"(v.w) : "memory");
}
__device__ __forceinline__ void red_add_v2(float* p, float a, float b) {
    asm volatile("red.global.add.v2.f32 [%0], {%1, %2};"
                 :: "l"(p), "f"(a), "f"(b) : "memory");
}

// ---------------- GEMM 0: x1 = relu(x[N,128] @ W0 + b0); Z0 = S*project(x1);
//                  also zero g_agg, g_pool, g_stats ----------------
__global__ void k_gemm0(const float* __restrict__ xin,
                        const float* __restrict__ W0,
                        const float* __restrict__ b0) {
    __shared__ __align__(16) float xs[64 * 64];
    __shared__ __align__(16) float Ws[64 * 64];
    int t = threadIdx.x;
    int R0 = blockIdx.x * 64;

    // zero scratch regions (coalesced float4 stores)
    {
        unsigned base = blockIdx.x * 4096u + t * 4u;
        float4 z4 = make_float4(0.f, 0.f, 0.f, 0.f);
#pragma unroll
        for (int i = 0; i < 4; i++) {
            unsigned idx = base + i * 1024u;
            if (idx < NN * DD) *(float4*)&g_agg[idx] = z4;
        }
        if (blockIdx.x < 128) {
            unsigned p = blockIdx.x * 256u + t;
            g_pool[p] = 0.f;
        }
        if (blockIdx.x == 0 && t < 128) g_stats[t] = 0.f;
    }

    int c4 = (t & 15) * 4;
    int rb = (t >> 4) * 4;
    float acc[4][4] = {};
    for (int kb = 0; kb < 128; kb += 64) {
#pragma unroll
        for (int i2 = 0; i2 < 16; i2++) {
            int idx = t + i2 * 256;
            int r = idx >> 6, c = idx & 63;
            int gr = R0 + r;
            xs[idx] = (gr < NN) ? xin[gr * 128 + kb + c] : 0.f;
            Ws[idx] = W0[(kb + r) * 64 + c];
        }
        __syncthreads();
#pragma unroll 8
        for (int k = 0; k < 64; k++) {
            float4 w = *(const float4*)&Ws[k * 64 + c4];
            float xr[4];
#pragma unroll
            for (int r = 0; r < 4; r++) xr[r] = xs[(rb + r) * 64 + k];
#pragma unroll
            for (int r = 0; r < 4; r++) {
                acc[r][0] = fmaf(xr[r], w.x, acc[r][0]);
                acc[r][1] = fmaf(xr[r], w.y, acc[r][1]);
                acc[r][2] = fmaf(xr[r], w.z, acc[r][2]);
                acc[r][3] = fmaf(xr[r], w.w, acc[r][3]);
            }
        }
        __syncthreads();
    }
    float4 bb = *(const float4*)&b0[c4];
    float o[4][4];
    float pr[4];
#pragma unroll
    for (int r = 0; r < 4; r++) {
        o[r][0] = fmaxf(acc[r][0] + bb.x, 0.f);
        o[r][1] = fmaxf(acc[r][1] + bb.y, 0.f);
        o[r][2] = fmaxf(acc[r][2] + bb.z, 0.f);
        o[r][3] = fmaxf(acc[r][3] + bb.w, 0.f);
        pr[r] = o[r][0]*o[r][0] + o[r][1]*o[r][1] + o[r][2]*o[r][2] + o[r][3]*o[r][3];
    }
    // reduce row sumsq across the 16 threads sharing this row group
#pragma unroll
    for (int m = 1; m < 16; m <<= 1) {
#pragma unroll
        for (int r = 0; r < 4; r++) pr[r] += __shfl_xor_sync(0xffffffffu, pr[r], m);
    }
#pragma unroll
    for (int r = 0; r < 4; r++) {
        int gr = R0 + rb + r;
        if (gr < NN) {
            *(float4*)&g_x[gr * 64 + c4] = make_float4(o[r][0], o[r][1], o[r][2], o[r][3]);
            float cn = fmaxf(sqrtf(pr[r]), 1e-15f);
            float f = (cn > 0.996f) ? (0.996f / cn) : 1.0f;
            f *= SCALING_F;
            *(float4*)&g_Z[0][gr * 64 + c4] =
                make_float4(o[r][0]*f, o[r][1]*f, o[r][2]*f, o[r][3]*f);
        }
    }
}

// ---------------- edge scatter: agg[dst] += x[src] (v4 RED); block 0 zeros stats ----------------
__global__ void k_edge(const int* __restrict__ ei) {
    unsigned tid = blockIdx.x * 256u + threadIdx.x;
    if (blockIdx.x == 0 && threadIdx.x < 128) g_stats[threadIdx.x] = 0.f;
    unsigned e = tid >> 4;       // edge id
    unsigned q = tid & 15u;      // dim quad (4 floats)
    int s = __ldg(&ei[e]);
    int dn = __ldg(&ei[EE + e]);
    float4 v = *(const float4*)&g_x[(unsigned)s * 64u + q * 4u];
    red_add_v4(&g_agg[(unsigned)dn * 64u + q * 4u], v);
}

// ---------------- GEMM A: h = relu((x+agg) @ W1 + b1); BN stats; rezero agg ----------------
__global__ void k_gemmA(const float* __restrict__ W, const float* __restrict__ b) {
    __shared__ __align__(16) float xs[64 * 64];
    __shared__ __align__(16) float Ws[64 * 64];
    __shared__ float s_sum[64], s_sq[64];
    int t = threadIdx.x;
    int R0 = blockIdx.x * 64;
    if (t < 64) { s_sum[t] = 0.f; s_sq[t] = 0.f; }
#pragma unroll
    for (int i2 = 0; i2 < 16; i2++) {
        int idx = t + i2 * 256;
        int r = idx >> 6, c = idx & 63;
        int gr = R0 + r;
        if (gr < NN) {
            xs[idx] = g_x[gr * 64 + c] + g_agg[gr * 64 + c];
            g_agg[gr * 64 + c] = 0.f;     // rezero for next layer's scatter
        } else xs[idx] = 0.f;
        Ws[idx] = W[idx];
    }
    __syncthreads();
    int c4 = (t & 15) * 4;
    int rb = (t >> 4) * 4;
    float acc[4][4] = {};
#pragma unroll 8
    for (int k = 0; k < 64; k++) {
        float4 w = *(const float4*)&Ws[k * 64 + c4];
        float xr[4];
#pragma unroll
        for (int r = 0; r < 4; r++) xr[r] = xs[(rb + r) * 64 + k];
#pragma unroll
        for (int r = 0; r < 4; r++) {
            acc[r][0] = fmaf(xr[r], w.x, acc[r][0]);
            acc[r][1] = fmaf(xr[r], w.y, acc[r][1]);
            acc[r][2] = fmaf(xr[r], w.z, acc[r][2]);
            acc[r][3] = fmaf(xr[r], w.w, acc[r][3]);
        }
    }
    float4 bb = *(const float4*)&b[c4];
    float ps[4] = {}, pq[4] = {};
#pragma unroll
    for (int r = 0; r < 4; r++) {
        int gr = R0 + rb + r;
        float o[4];
        o[0] = fmaxf(acc[r][0] + bb.x, 0.f);
        o[1] = fmaxf(acc[r][1] + bb.y, 0.f);
        o[2] = fmaxf(acc[r][2] + bb.z, 0.f);
        o[3] = fmaxf(acc[r][3] + bb.w, 0.f);
        if (gr < NN) {
            *(float4*)&g_h[gr * 64 + c4] = make_float4(o[0], o[1], o[2], o[3]);
#pragma unroll
            for (int j = 0; j < 4; j++) { ps[j] += o[j]; pq[j] += o[j] * o[j]; }
        }
    }
#pragma unroll
    for (int j = 0; j < 4; j++) {
        atomicAdd(&s_sum[c4 + j], ps[j]);
        atomicAdd(&s_sq[c4 + j], pq[j]);
    }
    __syncthreads();
    if (t < 64) {
        atomicAdd(&g_stats[t], s_sum[t]);
        atomicAdd(&g_stats[64 + t], s_sq[t]);
    }
}

// ---------------- GEMM B + hyperbolic update (fused) ----------------
__global__ void k_gemmB(const float* __restrict__ W, const float* __restrict__ b,
                        const float* __restrict__ gamma, const float* __restrict__ beta,
                        const int* __restrict__ batch, int iter, int last) {
    __shared__ __align__(16) float xs[64 * 64];
    __shared__ __align__(16) float Ws[64 * 64];
    __shared__ float sca[64], shi[64];
    int t = threadIdx.x;
    int R0 = blockIdx.x * 64;
    if (t < 64) {
        float mean = g_stats[t] * (1.0f / NN);
        float var = g_stats[64 + t] * (1.0f / NN) - mean * mean;
        float inv = rsqrtf(var + 1e-5f);
        float s = gamma[t] * inv;
        sca[t] = s;
        shi[t] = beta[t] - mean * s;
    }
    __syncthreads();
#pragma unroll
    for (int i2 = 0; i2 < 16; i2++) {
        int idx = t + i2 * 256;
        int r = idx >> 6, c = idx & 63;
        int gr = R0 + r;
        xs[idx] = (gr < NN) ? g_h[gr * 64 + c] * sca[c] + shi[c] : 0.f;
        Ws[idx] = W[idx];
    }
    __syncthreads();
    int c4 = (t & 15) * 4;
    int rb = (t >> 4) * 4;
    float acc[4][4] = {};
#pragma unroll 8
    for (int k = 0; k < 64; k++) {
        float4 w = *(const float4*)&Ws[k * 64 + c4];
        float xr[4];
#pragma unroll
        for (int r = 0; r < 4; r++) xr[r] = xs[(rb + r) * 64 + k];
#pragma unroll
        for (int r = 0; r < 4; r++) {
            acc[r][0] = fmaf(xr[r], w.x, acc[r][0]);
            acc[r][1] = fmaf(xr[r], w.y, acc[r][1]);
            acc[r][2] = fmaf(xr[r], w.z, acc[r][2]);
            acc[r][3] = fmaf(xr[r], w.w, acc[r][3]);
        }
    }
    __syncthreads();   // done reading xs; reuse it for the output tile
    float4 bb = *(const float4*)&b[c4];
#pragma unroll
    for (int r = 0; r < 4; r++) {
        float o[4];
        o[0] = fmaxf(acc[r][0] + bb.x, 0.f);
        o[1] = fmaxf(acc[r][1] + bb.y, 0.f);
        o[2] = fmaxf(acc[r][2] + bb.z, 0.f);
        o[3] = fmaxf(acc[r][3] + bb.w, 0.f);
        if (c4 + 3 == 63) o[3] = 0.f;   // x[:, -1] = 0
        *(float4*)&xs[(rb + r) * 64 + c4] = make_float4(o[0], o[1], o[2], o[3]);
        int gr = R0 + rb + r;
        if (gr < NN)
            *(float4*)&g_x[gr * 64 + c4] = make_float4(o[0], o[1], o[2], o[3]);
    }
    __syncthreads();

    // ---- hyperbolic update: warp w handles rows w*8 .. w*8+7 of this tile ----
    int wid = t >> 5;
    int lane = t & 31;
    int icur = iter;
    int inew = (iter + 1) % 3;
    int ipar = (iter + 2) % 3;
    const float2* zc2 = (const float2*)g_Z[icur];
    const float2* zp2 = (const float2*)g_Z[ipar];
    float2* zn2 = (float2*)g_Z[inew];

    for (int i = 0; i < 8; i++) {
        int rr = wid * 8 + i;
        int gr = R0 + rr;
        if (gr >= NN) break;
        int off = gr * 32 + lane;
        float2 xv = *(const float2*)&xs[rr * 64 + lane * 2];
        float2 mc = zc2[off];
        float2 pp = (iter == 0) ? make_float2(0.f, 0.f) : zp2[off];

        // z_children = SCALING * project(x)
        float n2 = warp_sum(xv.x * xv.x + xv.y * xv.y);
        float cn = fmaxf(sqrtf(n2), 1e-15f);
        float f = (cn > 0.996f) ? (0.996f / cn) : 1.0f;
        f *= SCALING_F;
        float2 zc = make_float2(xv.x * f, xv.y * f);

        // a = mu / cmin(||mu||^2)
        float mn2 = fmaxf(warp_sum(mc.x * mc.x + mc.y * mc.y), 1e-15f);
        float2 a = make_float2(mc.x / mn2, mc.y / mn2);
        float a2 = warp_sum(a.x * a.x + a.y * a.y);
        float r2 = a2 - 1.f;

        // z_parent' = isometric_transform(z_parent, a)
        float2 u = make_float2(pp.x - a.x, pp.y - a.y);
        float un2 = fmaxf(warp_sum(u.x * u.x + u.y * u.y), 1e-15f);
        float s1 = r2 / un2;
        float2 zp = make_float2(s1 * u.x + a.x, s1 * u.y + a.y);

        // reflect_through_zero(zp, e63, zc)
        float pn = fmaxf(sqrtf(warp_sum(zp.x * zp.x + zp.y * zp.y)), 1e-15f);
        float2 p_ = make_float2(zp.x / pn, zp.y / pn);
        float2 r = make_float2(-p_.x, -p_.y);
        if (lane == 31) r.y += 1.0f;
        float num = warp_sum(r.x * zc.x + r.y * zc.y);
        float den = warp_sum(r.x * r.x + r.y * r.y);
        float m = num / den;
        float2 zcc = make_float2(zc.x - 2.f * r.x * m, zc.y - 2.f * r.y * m);

        // z_all = isometric_transform(zcc, a)
        float2 u2 = make_float2(zcc.x - a.x, zcc.y - a.y);
        float u2n = fmaxf(warp_sum(u2.x * u2.x + u2.y * u2.y), 1e-15f);
        float s2 = r2 / u2n;
        float2 zn = make_float2(s2 * u2.x + a.x, s2 * u2.y + a.y);
        zn2[off] = zn;

        if (last) {
            float yn = fmaxf(sqrtf(warp_sum(zn.x * zn.x + zn.y * zn.y)), 1e-15f);
            float tt = fminf(yn, 1.0f);
            float sc = atanhf(tt) / yn;
            int bg = __ldg(&batch[gr]);
            red_add_v2(&g_pool[bg * 64 + lane * 2], zn.x * sc, zn.y * sc);
        }
    }
}

// ---------------- head MLP + log_softmax (block per graph) ----------------
__global__ void k_head(const float* __restrict__ fc1W, const float* __restrict__ fc1b,
                       const float* __restrict__ fc2W, const float* __restrict__ fc2b,
                       const float* __restrict__ fc3W, const float* __restrict__ fc3b,
                       float* __restrict__ out) {
    __shared__ float sp[64], h1[128], h2[64], lo[10];
    int g = blockIdx.x;
    int t = threadIdx.x;
    if (t < 64) sp[t] = g_pool[g * 64 + t];
    __syncthreads();
    {
        float acc = fc1b[t];
#pragma unroll 8
        for (int k = 0; k < 64; k++) acc = fmaf(sp[k], fc1W[k * 128 + t], acc);
        h1[t] = fmaxf(acc, 0.f);
    }
    __syncthreads();
    if (t < 64) {
        float acc = fc2b[t];
#pragma unroll 8
        for (int k = 0; k < 128; k++) acc = fmaf(h1[k], fc2W[k * 64 + t], acc);
        h2[t] = fmaxf(acc, 0.f);
    }
    __syncthreads();
    if (t < 10) {
        float acc = fc3b[t];
#pragma unroll 8
        for (int k = 0; k < 64; k++) acc = fmaf(h2[k], fc3W[k * 10 + t], acc);
        lo[t] = acc;
    }
    __syncthreads();
    if (t == 0) {
        float mx = lo[0];
#pragma unroll
        for (int c = 1; c < 10; c++) mx = fmaxf(mx, lo[c]);
        float s = 0.f;
#pragma unroll
        for (int c = 0; c < 10; c++) s += expf(lo[c] - mx);
        float lse = mx + logf(s);
#pragma unroll
        for (int c = 0; c < 10; c++) out[g * 10 + c] = lo[c] - lse;
    }
}

// ---------------- launch ----------------
extern "C" void kernel_launch(void* const* d_in, const int* in_sizes, int n_in,
                              void* d_out, int out_size) {
    const float* x     = (const float*)d_in[0];
    const int*   ei    = (const int*)d_in[1];
    const int*   batch = (const int*)d_in[2];
    const float* W0    = (const float*)d_in[3];
    const float* b0    = (const float*)d_in[4];
    const float* cW1   = (const float*)d_in[5];
    const float* cb1   = (const float*)d_in[6];
    const float* gamma = (const float*)d_in[7];
    const float* beta  = (const float*)d_in[8];
    const float* cW2   = (const float*)d_in[9];
    const float* cb2   = (const float*)d_in[10];
    const float* fc1W  = (const float*)d_in[11];
    const float* fc1b  = (const float*)d_in[12];
    const float* fc2W  = (const float*)d_in[13];
    const float* fc2b  = (const float*)d_in[14];
    const float* fc3W  = (const float*)d_in[15];
    const float* fc3b  = (const float*)d_in[16];
    float* out = (float*)d_out;

    const int gemmGrid = (NN + 63) / 64;         // 782
    const int edgeGrid = (EE * 16) / 256;        // 50000

    k_gemm0<<<gemmGrid, 256>>>(x, W0, b0);
    for (int l = 0; l < 3; l++) {
        k_edge<<<edgeGrid, 256>>>(ei);
        k_gemmA<<<gemmGrid, 256>>>(cW1 + l * 64 * 64, cb1 + l * 64);
        k_gemmB<<<gemmGrid, 256>>>(cW2 + l * 64 * 64, cb2 + l * 64,
                                   gamma + l * 64, beta + l * 64,
                                   batch, l, (l == 2) ? 1 : 0);
    }
    k_head<<<512, 128>>>(fc1W, fc1b, fc2W, fc2b, fc3W, fc3b, out);
}

// round 5
// speedup vs baseline: 1.6402x; 1.2369x over previous
#include <cuda_runtime.h>
#include <math.h>

#define NN 50000
#define EE 800000
#define DIN 128
#define DD 64
#define GG 512
#define TR 128            // GEMM tile rows
#define SCALING_F 0.46211715726000974f

// ---------------- scratch (static device globals; no allocation) ----------------
__device__ __align__(16) float g_x[NN * DD];
__device__ __align__(16) float g_h[NN * DD];
__device__ __align__(16) float g_agg[NN * DD];
__device__ __align__(16) float g_Z[3][NN * DD];
__device__ __align__(16) float g_stats[2 * DD];
__device__ __align__(16) float g_pool[GG * DD];

__device__ __forceinline__ float warp_sum(float v) {
#pragma unroll
    for (int o = 16; o; o >>= 1) v += __shfl_xor_sync(0xffffffffu, v, o);
    return v;
}

__device__ __forceinline__ void red_add_v4(float* p, float4 v) {
    asm volatile("red.global.add.v4.f32 [%0], {%1, %2, %3, %4};"
                 :: "l"(p), "f"(v.x), "f"(v.y), "f"(v.z), "f"(v.w) : "memory");
}
__device__ __forceinline__ void red_add_v2(float* p, float a, float b) {
    asm volatile("red.global.add.v2.f32 [%0], {%1, %2};"
                 :: "l"(p), "f"(a), "f"(b) : "memory");
}

#define FMA4(accr, xvk, wq)                       \
    accr[0] = fmaf(xvk, wq.x, accr[0]);           \
    accr[1] = fmaf(xvk, wq.y, accr[1]);           \
    accr[2] = fmaf(xvk, wq.z, accr[2]);           \
    accr[3] = fmaf(xvk, wq.w, accr[3]);

// Shared inner product: acc[8][4] += xs[rb..rb+7][k] * Ws[k][c4..c4+3]
__device__ __forceinline__ void mma_core(const float* xs, const float* Ws,
                                         int rb, int c4, float acc[8][4]) {
#pragma unroll 2
    for (int k = 0; k < 64; k += 4) {
        float4 w0 = *(const float4*)&Ws[k * 64 + c4];
        float4 w1 = *(const float4*)&Ws[(k + 1) * 64 + c4];
        float4 w2 = *(const float4*)&Ws[(k + 2) * 64 + c4];
        float4 w3 = *(const float4*)&Ws[(k + 3) * 64 + c4];
#pragma unroll
        for (int r = 0; r < 8; r++) {
            float4 xv = *(const float4*)&xs[(rb + r) * 64 + k];
            FMA4(acc[r], xv.x, w0);
            FMA4(acc[r], xv.y, w1);
            FMA4(acc[r], xv.z, w2);
            FMA4(acc[r], xv.w, w3);
        }
    }
}

// ---------------- GEMM 0: x1 = relu(x[N,128] @ W0 + b0); Z0 = S*project(x1);
//                  also zero g_agg, g_pool, g_stats ----------------
__global__ __launch_bounds__(256, 3) void k_gemm0(const float* __restrict__ xin,
                                                  const float* __restrict__ W0,
                                                  const float* __restrict__ b0) {
    __shared__ __align__(16) float xs[TR * 64];
    __shared__ __align__(16) float Ws[64 * 64];
    int t = threadIdx.x;
    int R0 = blockIdx.x * TR;
    float4 z4 = make_float4(0.f, 0.f, 0.f, 0.f);

    // zero scratch regions
#pragma unroll
    for (int i = 0; i < 8; i++) {
        unsigned idx4 = blockIdx.x * 2048u + i * 256u + t;
        if (idx4 < (NN * DD / 4)) ((float4*)g_agg)[idx4] = z4;
    }
    if (blockIdx.x < 32) ((float4*)g_pool)[blockIdx.x * 256u + t] = z4;
    if (blockIdx.x == 0 && t < 128) g_stats[t] = 0.f;

    int tx = t & 15, ty = t >> 4;
    int c4 = tx * 4, rb = ty * 8;
    float acc[8][4] = {};
    for (int kb = 0; kb < 128; kb += 64) {
        if (kb) __syncthreads();
#pragma unroll
        for (int i = 0; i < 8; i++) {
            int idx4 = t + i * 256;
            int r = idx4 >> 4, cq = idx4 & 15;
            int gr = R0 + r;
            float4 v = (gr < NN) ? *(const float4*)&xin[gr * 128 + kb + cq * 4] : z4;
            *(float4*)&xs[r * 64 + cq * 4] = v;
        }
#pragma unroll
        for (int i = 0; i < 4; i++) {
            int idx4 = t + i * 256;
            int r = idx4 >> 4, cq = idx4 & 15;
            *(float4*)&Ws[r * 64 + cq * 4] = *(const float4*)&W0[(kb + r) * 64 + cq * 4];
        }
        __syncthreads();
        mma_core(xs, Ws, rb, c4, acc);
    }
    float4 bb = *(const float4*)&b0[c4];
    float o[8][4], pr[8];
#pragma unroll
    for (int r = 0; r < 8; r++) {
        o[r][0] = fmaxf(acc[r][0] + bb.x, 0.f);
        o[r][1] = fmaxf(acc[r][1] + bb.y, 0.f);
        o[r][2] = fmaxf(acc[r][2] + bb.z, 0.f);
        o[r][3] = fmaxf(acc[r][3] + bb.w, 0.f);
        pr[r] = o[r][0]*o[r][0] + o[r][1]*o[r][1] + o[r][2]*o[r][2] + o[r][3]*o[r][3];
    }
#pragma unroll
    for (int m = 1; m < 16; m <<= 1) {
#pragma unroll
        for (int r = 0; r < 8; r++) pr[r] += __shfl_xor_sync(0xffffffffu, pr[r], m);
    }
#pragma unroll
    for (int r = 0; r < 8; r++) {
        int gr = R0 + rb + r;
        if (gr < NN) {
            *(float4*)&g_x[gr * 64 + c4] = make_float4(o[r][0], o[r][1], o[r][2], o[r][3]);
            float cn = fmaxf(sqrtf(pr[r]), 1e-15f);
            float f = (cn > 0.996f) ? (0.996f / cn) : 1.0f;
            f *= SCALING_F;
            *(float4*)&g_Z[0][gr * 64 + c4] =
                make_float4(o[r][0]*f, o[r][1]*f, o[r][2]*f, o[r][3]*f);
        }
    }
}

// ---------------- edge scatter: agg[dst] += x[src] (v4 RED); block 0 zeros stats ----------------
__global__ void k_edge(const int* __restrict__ ei) {
    unsigned tid = blockIdx.x * 256u + threadIdx.x;
    if (blockIdx.x == 0 && threadIdx.x < 128) g_stats[threadIdx.x] = 0.f;
    unsigned e = tid >> 4;
    unsigned q = tid & 15u;
    int s = __ldg(&ei[e]);
    int dn = __ldg(&ei[EE + e]);
    float4 v = *(const float4*)&g_x[(unsigned)s * 64u + q * 4u];
    red_add_v4(&g_agg[(unsigned)dn * 64u + q * 4u], v);
}

// ---------------- GEMM A: h = relu((x+agg) @ W1 + b1); BN stats; rezero agg ----------------
__global__ __launch_bounds__(256, 3) void k_gemmA(const float* __restrict__ W,
                                                  const float* __restrict__ b) {
    __shared__ __align__(16) float xs[TR * 64];
    __shared__ __align__(16) float Ws[64 * 64];
    __shared__ float s_sum[64], s_sq[64];
    int t = threadIdx.x;
    int R0 = blockIdx.x * TR;
    float4 z4 = make_float4(0.f, 0.f, 0.f, 0.f);
    if (t < 64) { s_sum[t] = 0.f; s_sq[t] = 0.f; }
#pragma unroll
    for (int i = 0; i < 8; i++) {
        int idx4 = t + i * 256;
        int r = idx4 >> 4, cq = idx4 & 15;
        int gr = R0 + r;
        float4 v = z4;
        if (gr < NN) {
            float4 a = *(const float4*)&g_x[gr * 64 + cq * 4];
            float4 g = *(const float4*)&g_agg[gr * 64 + cq * 4];
            v = make_float4(a.x + g.x, a.y + g.y, a.z + g.z, a.w + g.w);
            *(float4*)&g_agg[gr * 64 + cq * 4] = z4;   // rezero for next scatter
        }
        *(float4*)&xs[r * 64 + cq * 4] = v;
    }
#pragma unroll
    for (int i = 0; i < 4; i++) {
        int idx4 = t + i * 256;
        *(float4*)&Ws[idx4 * 4] = *(const float4*)&W[idx4 * 4];
    }
    __syncthreads();
    int tx = t & 15, ty = t >> 4;
    int c4 = tx * 4, rb = ty * 8;
    float acc[8][4] = {};
    mma_core(xs, Ws, rb, c4, acc);

    float4 bb = *(const float4*)&b[c4];
    float ps[4] = {}, pq[4] = {};
#pragma unroll
    for (int r = 0; r < 8; r++) {
        int gr = R0 + rb + r;
        float o[4];
        o[0] = fmaxf(acc[r][0] + bb.x, 0.f);
        o[1] = fmaxf(acc[r][1] + bb.y, 0.f);
        o[2] = fmaxf(acc[r][2] + bb.z, 0.f);
        o[3] = fmaxf(acc[r][3] + bb.w, 0.f);
        if (gr < NN) {
            *(float4*)&g_h[gr * 64 + c4] = make_float4(o[0], o[1], o[2], o[3]);
#pragma unroll
            for (int j = 0; j < 4; j++) { ps[j] += o[j]; pq[j] += o[j] * o[j]; }
        }
    }
#pragma unroll
    for (int j = 0; j < 4; j++) {
        atomicAdd(&s_sum[c4 + j], ps[j]);
        atomicAdd(&s_sq[c4 + j], pq[j]);
    }
    __syncthreads();
    if (t < 64) {
        atomicAdd(&g_stats[t], s_sum[t]);
        atomicAdd(&g_stats[64 + t], s_sq[t]);
    }
}

// ---------------- GEMM B + hyperbolic update (fused) ----------------
__global__ __launch_bounds__(256, 3) void k_gemmB(const float* __restrict__ W,
                                                  const float* __restrict__ b,
                                                  const float* __restrict__ gamma,
                                                  const float* __restrict__ beta,
                                                  const int* __restrict__ batch,
                                                  int iter, int last) {
    __shared__ __align__(16) float xs[TR * 64];
    __shared__ __align__(16) float Ws[64 * 64];
    __shared__ float sca[64], shi[64];
    int t = threadIdx.x;
    int R0 = blockIdx.x * TR;
    if (t < 64) {
        float mean = g_stats[t] * (1.0f / NN);
        float var = g_stats[64 + t] * (1.0f / NN) - mean * mean;
        float inv = rsqrtf(var + 1e-5f);
        float s = gamma[t] * inv;
        sca[t] = s;
        shi[t] = beta[t] - mean * s;
    }
    __syncthreads();
#pragma unroll
    for (int i = 0; i < 8; i++) {
        int idx4 = t + i * 256;
        int r = idx4 >> 4, cq = idx4 & 15;
        int gr = R0 + r;
        float4 v = make_float4(shi[cq*4], shi[cq*4+1], shi[cq*4+2], shi[cq*4+3]);
        if (gr < NN) {
            float4 h = *(const float4*)&g_h[gr * 64 + cq * 4];
            v.x = fmaf(h.x, sca[cq*4],   v.x);
            v.y = fmaf(h.y, sca[cq*4+1], v.y);
            v.z = fmaf(h.z, sca[cq*4+2], v.z);
            v.w = fmaf(h.w, sca[cq*4+3], v.w);
        } else v = make_float4(0.f, 0.f, 0.f, 0.f);
        *(float4*)&xs[r * 64 + cq * 4] = v;
    }
#pragma unroll
    for (int i = 0; i < 4; i++) {
        int idx4 = t + i * 256;
        *(float4*)&Ws[idx4 * 4] = *(const float4*)&W[idx4 * 4];
    }
    __syncthreads();
    int tx = t & 15, ty = t >> 4;
    int c4 = tx * 4, rb = ty * 8;
    float acc[8][4] = {};
    mma_core(xs, Ws, rb, c4, acc);
    __syncthreads();   // done reading xs; reuse for output tile

    float4 bb = *(const float4*)&b[c4];
#pragma unroll
    for (int r = 0; r < 8; r++) {
        float o[4];
        o[0] = fmaxf(acc[r][0] + bb.x, 0.f);
        o[1] = fmaxf(acc[r][1] + bb.y, 0.f);
        o[2] = fmaxf(acc[r][2] + bb.z, 0.f);
        o[3] = fmaxf(acc[r][3] + bb.w, 0.f);
        if (c4 + 3 == 63) o[3] = 0.f;   // x[:, -1] = 0
        *(float4*)&xs[(rb + r) * 64 + c4] = make_float4(o[0], o[1], o[2], o[3]);
        int gr = R0 + rb + r;
        if (gr < NN)
            *(float4*)&g_x[gr * 64 + c4] = make_float4(o[0], o[1], o[2], o[3]);
    }
    __syncthreads();

    // ---- hyperbolic update: warp w handles rows w*16 .. w*16+15 ----
    int wid = t >> 5;
    int lane = t & 31;
    int icur = iter;
    int inew = (iter + 1) % 3;
    int ipar = (iter + 2) % 3;
    const float2* zc2 = (const float2*)g_Z[icur];
    const float2* zp2 = (const float2*)g_Z[ipar];
    float2* zn2 = (float2*)g_Z[inew];

    for (int i = 0; i < 16; i++) {
        int rr = wid * 16 + i;
        int gr = R0 + rr;
        if (gr >= NN) break;
        int off = gr * 32 + lane;
        float2 xv = *(const float2*)&xs[rr * 64 + lane * 2];
        float2 mc = zc2[off];
        float2 pp = (iter == 0) ? make_float2(0.f, 0.f) : zp2[off];

        // z_children = SCALING * project(x)
        float n2 = warp_sum(xv.x * xv.x + xv.y * xv.y);
        float cn = fmaxf(sqrtf(n2), 1e-15f);
        float f = (cn > 0.996f) ? (0.996f / cn) : 1.0f;
        f *= SCALING_F;
        float2 zc = make_float2(xv.x * f, xv.y * f);

        // a = mu / cmin(||mu||^2)
        float mn2 = fmaxf(warp_sum(mc.x * mc.x + mc.y * mc.y), 1e-15f);
        float2 a = make_float2(mc.x / mn2, mc.y / mn2);
        float a2 = warp_sum(a.x * a.x + a.y * a.y);
        float r2 = a2 - 1.f;

        // z_parent' = isometric_transform(z_parent, a)
        float2 u = make_float2(pp.x - a.x, pp.y - a.y);
        float un2 = fmaxf(warp_sum(u.x * u.x + u.y * u.y), 1e-15f);
        float s1 = r2 / un2;
        float2 zp = make_float2(s1 * u.x + a.x, s1 * u.y + a.y);

        // reflect_through_zero(zp, e63, zc)
        float pn = fmaxf(sqrtf(warp_sum(zp.x * zp.x + zp.y * zp.y)), 1e-15f);
        float2 p_ = make_float2(zp.x / pn, zp.y / pn);
        float2 r = make_float2(-p_.x, -p_.y);
        if (lane == 31) r.y += 1.0f;
        float num = warp_sum(r.x * zc.x + r.y * zc.y);
        float den = warp_sum(r.x * r.x + r.y * r.y);
        float m = num / den;
        float2 zcc = make_float2(zc.x - 2.f * r.x * m, zc.y - 2.f * r.y * m);

        // z_all = isometric_transform(zcc, a)
        float2 u2 = make_float2(zcc.x - a.x, zcc.y - a.y);
        float u2n = fmaxf(warp_sum(u2.x * u2.x + u2.y * u2.y), 1e-15f);
        float s2 = r2 / u2n;
        float2 zn = make_float2(s2 * u2.x + a.x, s2 * u2.y + a.y);
        zn2[off] = zn;

        if (last) {
            float yn = fmaxf(sqrtf(warp_sum(zn.x * zn.x + zn.y * zn.y)), 1e-15f);
            float tt = fminf(yn, 1.0f);
            float sc = atanhf(tt) / yn;
            int bg = __ldg(&batch[gr]);
            red_add_v2(&g_pool[bg * 64 + lane * 2], zn.x * sc, zn.y * sc);
        }
    }
}

// ---------------- head MLP + log_softmax (block per graph) ----------------
__global__ void k_head(const float* __restrict__ fc1W, const float* __restrict__ fc1b,
                       const float* __restrict__ fc2W, const float* __restrict__ fc2b,
                       const float* __restrict__ fc3W, const float* __restrict__ fc3b,
                       float* __restrict__ out) {
    __shared__ float sp[64], h1[128], h2[64], lo[10];
    int g = blockIdx.x;
    int t = threadIdx.x;
    if (t < 64) sp[t] = g_pool[g * 64 + t];
    __syncthreads();
    {
        float acc = fc1b[t];
#pragma unroll 8
        for (int k = 0; k < 64; k++) acc = fmaf(sp[k], fc1W[k * 128 + t], acc);
        h1[t] = fmaxf(acc, 0.f);
    }
    __syncthreads();
    if (t < 64) {
        float acc = fc2b[t];
#pragma unroll 8
        for (int k = 0; k < 128; k++) acc = fmaf(h1[k], fc2W[k * 64 + t], acc);
        h2[t] = fmaxf(acc, 0.f);
    }
    __syncthreads();
    if (t < 10) {
        float acc = fc3b[t];
#pragma unroll 8
        for (int k = 0; k < 64; k++) acc = fmaf(h2[k], fc3W[k * 10 + t], acc);
        lo[t] = acc;
    }
    __syncthreads();
    if (t == 0) {
        float mx = lo[0];
#pragma unroll
        for (int c = 1; c < 10; c++) mx = fmaxf(mx, lo[c]);
        float s = 0.f;
#pragma unroll
        for (int c = 0; c < 10; c++) s += expf(lo[c] - mx);
        float lse = mx + logf(s);
#pragma unroll
        for (int c = 0; c < 10; c++) out[g * 10 + c] = lo[c] - lse;
    }
}

// ---------------- launch ----------------
extern "C" void kernel_launch(void* const* d_in, const int* in_sizes, int n_in,
                              void* d_out, int out_size) {
    const float* x     = (const float*)d_in[0];
    const int*   ei    = (const int*)d_in[1];
    const int*   batch = (const int*)d_in[2];
    const float* W0    = (const float*)d_in[3];
    const float* b0    = (const float*)d_in[4];
    const float* cW1   = (const float*)d_in[5];
    const float* cb1   = (const float*)d_in[6];
    const float* gamma = (const float*)d_in[7];
    const float* beta  = (const float*)d_in[8];
    const float* cW2   = (const float*)d_in[9];
    const float* cb2   = (const float*)d_in[10];
    const float* fc1W  = (const float*)d_in[11];
    const float* fc1b  = (const float*)d_in[12];
    const float* fc2W  = (const float*)d_in[13];
    const float* fc2b  = (const float*)d_in[14];
    const float* fc3W  = (const float*)d_in[15];
    const float* fc3b  = (const float*)d_in[16];
    float* out = (float*)d_out;

    const int gemmGrid = (NN + TR - 1) / TR;     // 391
    const int edgeGrid = (EE * 16) / 256;        // 50000

    k_gemm0<<<gemmGrid, 256>>>(x, W0, b0);
    for (int l = 0; l < 3; l++) {
        k_edge<<<edgeGrid, 256>>>(ei);
        k_gemmA<<<gemmGrid, 256>>>(cW1 + l * 64 * 64, cb1 + l * 64);
        k_gemmB<<<gemmGrid, 256>>>(cW2 + l * 64 * 64, cb2 + l * 64,
                                   gamma + l * 64, beta + l * 64,
                                   batch, l, (l == 2) ? 1 : 0);
    }
    k_head<<<512, 128>>>(fc1W, fc1b, fc2W, fc2b, fc3W, fc3b, out);
}

// round 7
// speedup vs baseline: 1.7587x; 1.0722x over previous
#include <cuda_runtime.h>
#include <math.h>

#define NN 50000
#define EE 800000
#define DIN 128
#define DD 64
#define GG 512
#define TR 128            // GEMM tile rows
#define SCALING_F 0.46211715726000974f

// ---------------- scratch (static device globals; no allocation) ----------------
__device__ __align__(16) float g_x[NN * DD];
__device__ __align__(16) float g_h[NN * DD];
__device__ __align__(16) float g_agg[NN * DD];
__device__ __align__(16) float g_Z[3][NN * DD];
__device__ __align__(16) float g_stats[2 * DD];
__device__ __align__(16) float g_pool[GG * DD];

__device__ __forceinline__ void red_add_v4(float* p, float4 v) {
    asm volatile("red.global.add.v4.f32 [%0], {%1, %2, %3, %4};"
                 :: "l"(p), "f"(v.x), "f"(v.y), "f"(v.z), "f"(v.w) : "memory");
}
__device__ __forceinline__ void red_add_v2(float* p, float a, float b) {
    asm volatile("red.global.add.v2.f32 [%0], {%1, %2};"
                 :: "l"(p), "f"(a), "f"(b) : "memory");
}

#define FMA4(accr, xvk, wq)                       \
    accr[0] = fmaf(xvk, wq.x, accr[0]);           \
    accr[1] = fmaf(xvk, wq.y, accr[1]);           \
    accr[2] = fmaf(xvk, wq.z, accr[2]);           \
    accr[3] = fmaf(xvk, wq.w, accr[3]);

// Shared inner product: acc[8][4] += xs[rb..rb+7][k] * Ws[k][c4..c4+3]
__device__ __forceinline__ void mma_core(const float* xs, const float* Ws,
                                         int rb, int c4, float acc[8][4]) {
#pragma unroll 2
    for (int k = 0; k < 64; k += 4) {
        float4 w0 = *(const float4*)&Ws[k * 64 + c4];
        float4 w1 = *(const float4*)&Ws[(k + 1) * 64 + c4];
        float4 w2 = *(const float4*)&Ws[(k + 2) * 64 + c4];
        float4 w3 = *(const float4*)&Ws[(k + 3) * 64 + c4];
#pragma unroll
        for (int r = 0; r < 8; r++) {
            float4 xv = *(const float4*)&xs[(rb + r) * 64 + k];
            FMA4(acc[r], xv.x, w0);
            FMA4(acc[r], xv.y, w1);
            FMA4(acc[r], xv.z, w2);
            FMA4(acc[r], xv.w, w3);
        }
    }
}

// ---------------- GEMM 0 ----------------
__global__ __launch_bounds__(256, 3) void k_gemm0(const float* __restrict__ xin,
                                                  const float* __restrict__ W0,
                                                  const float* __restrict__ b0) {
    __shared__ __align__(16) float xs[TR * 64];
    __shared__ __align__(16) float Ws[64 * 64];
    int t = threadIdx.x;
    int R0 = blockIdx.x * TR;
    float4 z4 = make_float4(0.f, 0.f, 0.f, 0.f);

#pragma unroll
    for (int i = 0; i < 8; i++) {
        unsigned idx4 = blockIdx.x * 2048u + i * 256u + t;
        if (idx4 < (NN * DD / 4)) ((float4*)g_agg)[idx4] = z4;
    }
    if (blockIdx.x < 32) ((float4*)g_pool)[blockIdx.x * 256u + t] = z4;
    if (blockIdx.x == 0 && t < 128) g_stats[t] = 0.f;

    int tx = t & 15, ty = t >> 4;
    int c4 = tx * 4, rb = ty * 8;
    float acc[8][4] = {};
    for (int kb = 0; kb < 128; kb += 64) {
        if (kb) __syncthreads();
#pragma unroll
        for (int i = 0; i < 8; i++) {
            int idx4 = t + i * 256;
            int r = idx4 >> 4, cq = idx4 & 15;
            int gr = R0 + r;
            float4 v = (gr < NN) ? *(const float4*)&xin[gr * 128 + kb + cq * 4] : z4;
            *(float4*)&xs[r * 64 + cq * 4] = v;
        }
#pragma unroll
        for (int i = 0; i < 4; i++) {
            int idx4 = t + i * 256;
            int r = idx4 >> 4, cq = idx4 & 15;
            *(float4*)&Ws[r * 64 + cq * 4] = *(const float4*)&W0[(kb + r) * 64 + cq * 4];
        }
        __syncthreads();
        mma_core(xs, Ws, rb, c4, acc);
    }
    float4 bb = *(const float4*)&b0[c4];
    float o[8][4], pr[8];
#pragma unroll
    for (int r = 0; r < 8; r++) {
        o[r][0] = fmaxf(acc[r][0] + bb.x, 0.f);
        o[r][1] = fmaxf(acc[r][1] + bb.y, 0.f);
        o[r][2] = fmaxf(acc[r][2] + bb.z, 0.f);
        o[r][3] = fmaxf(acc[r][3] + bb.w, 0.f);
        pr[r] = o[r][0]*o[r][0] + o[r][1]*o[r][1] + o[r][2]*o[r][2] + o[r][3]*o[r][3];
    }
#pragma unroll
    for (int m = 1; m < 16; m <<= 1) {
#pragma unroll
        for (int r = 0; r < 8; r++) pr[r] += __shfl_xor_sync(0xffffffffu, pr[r], m);
    }
#pragma unroll
    for (int r = 0; r < 8; r++) {
        int gr = R0 + rb + r;
        if (gr < NN) {
            *(float4*)&g_x[gr * 64 + c4] = make_float4(o[r][0], o[r][1], o[r][2], o[r][3]);
            float cn = fmaxf(sqrtf(pr[r]), 1e-15f);
            float f = (cn > 0.996f) ? (0.996f / cn) : 1.0f;
            f *= SCALING_F;
            *(float4*)&g_Z[0][gr * 64 + c4] =
                make_float4(o[r][0]*f, o[r][1]*f, o[r][2]*f, o[r][3]*f);
        }
    }
}

// ---------------- edge scatter ----------------
__global__ void k_edge(const int* __restrict__ ei) {
    unsigned tid = blockIdx.x * 256u + threadIdx.x;
    if (blockIdx.x == 0 && threadIdx.x < 128) g_stats[threadIdx.x] = 0.f;
    unsigned e = tid >> 4;
    unsigned q = tid & 15u;
    int s = __ldg(&ei[e]);
    int dn = __ldg(&ei[EE + e]);
    float4 v = *(const float4*)&g_x[(unsigned)s * 64u + q * 4u];
    red_add_v4(&g_agg[(unsigned)dn * 64u + q * 4u], v);
}

// ---------------- GEMM A ----------------
__global__ __launch_bounds__(256, 3) void k_gemmA(const float* __restrict__ W,
                                                  const float* __restrict__ b) {
    __shared__ __align__(16) float xs[TR * 64];
    __shared__ __align__(16) float Ws[64 * 64];
    __shared__ float s_sum[64], s_sq[64];
    int t = threadIdx.x;
    int R0 = blockIdx.x * TR;
    float4 z4 = make_float4(0.f, 0.f, 0.f, 0.f);
    if (t < 64) { s_sum[t] = 0.f; s_sq[t] = 0.f; }
#pragma unroll
    for (int i = 0; i < 8; i++) {
        int idx4 = t + i * 256;
        int r = idx4 >> 4, cq = idx4 & 15;
        int gr = R0 + r;
        float4 v = z4;
        if (gr < NN) {
            float4 a = *(const float4*)&g_x[gr * 64 + cq * 4];
            float4 g = *(const float4*)&g_agg[gr * 64 + cq * 4];
            v = make_float4(a.x + g.x, a.y + g.y, a.z + g.z, a.w + g.w);
            *(float4*)&g_agg[gr * 64 + cq * 4] = z4;
        }
        *(float4*)&xs[r * 64 + cq * 4] = v;
    }
#pragma unroll
    for (int i = 0; i < 4; i++) {
        int idx4 = t + i * 256;
        *(float4*)&Ws[idx4 * 4] = *(const float4*)&W[idx4 * 4];
    }
    __syncthreads();
    int tx = t & 15, ty = t >> 4;
    int c4 = tx * 4, rb = ty * 8;
    float acc[8][4] = {};
    mma_core(xs, Ws, rb, c4, acc);

    float4 bb = *(const float4*)&b[c4];
    float ps[4] = {}, pq[4] = {};
#pragma unroll
    for (int r = 0; r < 8; r++) {
        int gr = R0 + rb + r;
        float o[4];
        o[0] = fmaxf(acc[r][0] + bb.x, 0.f);
        o[1] = fmaxf(acc[r][1] + bb.y, 0.f);
        o[2] = fmaxf(acc[r][2] + bb.z, 0.f);
        o[3] = fmaxf(acc[r][3] + bb.w, 0.f);
        if (gr < NN) {
            *(float4*)&g_h[gr * 64 + c4] = make_float4(o[0], o[1], o[2], o[3]);
#pragma unroll
            for (int j = 0; j < 4; j++) { ps[j] += o[j]; pq[j] += o[j] * o[j]; }
        }
    }
#pragma unroll
    for (int j = 0; j < 4; j++) {
        atomicAdd(&s_sum[c4 + j], ps[j]);
        atomicAdd(&s_sq[c4 + j], pq[j]);
    }
    __syncthreads();
    if (t < 64) {
        atomicAdd(&g_stats[t], s_sum[t]);
        atomicAdd(&g_stats[64 + t], s_sq[t]);
    }
}

// ---------------- GEMM B + closed-form hyperbolic update ----------------
__global__ __launch_bounds__(256, 3) void k_gemmB(const float* __restrict__ W,
                                                  const float* __restrict__ b,
                                                  const float* __restrict__ gamma,
                                                  const float* __restrict__ beta,
                                                  const int* __restrict__ batch,
                                                  int iter, int last) {
    __shared__ __align__(16) float xs[TR * 64];
    __shared__ __align__(16) float Ws[64 * 64];
    __shared__ float sca[64], shi[64];
    int t = threadIdx.x;
    int R0 = blockIdx.x * TR;
    if (t < 64) {
        float mean = g_stats[t] * (1.0f / NN);
        float var = g_stats[64 + t] * (1.0f / NN) - mean * mean;
        float inv = rsqrtf(var + 1e-5f);
        float s = gamma[t] * inv;
        sca[t] = s;
        shi[t] = beta[t] - mean * s;
    }
    __syncthreads();
#pragma unroll
    for (int i = 0; i < 8; i++) {
        int idx4 = t + i * 256;
        int r = idx4 >> 4, cq = idx4 & 15;
        int gr = R0 + r;
        float4 v;
        if (gr < NN) {
            float4 h = *(const float4*)&g_h[gr * 64 + cq * 4];
            v.x = fmaf(h.x, sca[cq*4],   shi[cq*4]);
            v.y = fmaf(h.y, sca[cq*4+1], shi[cq*4+1]);
            v.z = fmaf(h.z, sca[cq*4+2], shi[cq*4+2]);
            v.w = fmaf(h.w, sca[cq*4+3], shi[cq*4+3]);
        } else v = make_float4(0.f, 0.f, 0.f, 0.f);
        *(float4*)&xs[r * 64 + cq * 4] = v;
    }
#pragma unroll
    for (int i = 0; i < 4; i++) {
        int idx4 = t + i * 256;
        *(float4*)&Ws[idx4 * 4] = *(const float4*)&W[idx4 * 4];
    }
    __syncthreads();
    int tx = t & 15, ty = t >> 4;
    int c4 = tx * 4, rb = ty * 8;
    float acc[8][4] = {};
    mma_core(xs, Ws, rb, c4, acc);
    __syncthreads();   // done reading xs; reuse for output tile

    float4 bb = *(const float4*)&b[c4];
#pragma unroll
    for (int r = 0; r < 8; r++) {
        float o[4];
        o[0] = fmaxf(acc[r][0] + bb.x, 0.f);
        o[1] = fmaxf(acc[r][1] + bb.y, 0.f);
        o[2] = fmaxf(acc[r][2] + bb.z, 0.f);
        o[3] = fmaxf(acc[r][3] + bb.w, 0.f);
        if (c4 + 3 == 63) o[3] = 0.f;   // x[:, -1] = 0
        *(float4*)&xs[(rb + r) * 64 + c4] = make_float4(o[0], o[1], o[2], o[3]);
        int gr = R0 + rb + r;
        if (gr < NN)
            *(float4*)&g_x[gr * 64 + c4] = make_float4(o[0], o[1], o[2], o[3]);
    }
    __syncthreads();

    // ---- hyperbolic update, closed form: zn = cx*x + cp*pp + cm*mc + ce*e63 ----
    int wid = t >> 5;
    int lane = t & 31;
    const float2* zc2 = (const float2*)g_Z[iter];
    const float2* zp2 = (const float2*)g_Z[(iter + 2) % 3];
    float2* zn2 = (float2*)g_Z[(iter + 1) % 3];

#pragma unroll 2
    for (int i = 0; i < 16; i++) {
        int rr = wid * 16 + i;
        int gr = R0 + rr;
        if (gr >= NN) break;
        int off = gr * 32 + lane;
        float2 xv = *(const float2*)&xs[rr * 64 + lane * 2];
        float2 mc = zc2[off];
        float2 pp = (iter == 0) ? make_float2(0.f, 0.f) : zp2[off];

        // 6 dot products via one interleaved butterfly
        float d0 = xv.x*xv.x + xv.y*xv.y;   // x.x
        float d1 = mc.x*mc.x + mc.y*mc.y;   // mc.mc
        float d2 = pp.x*pp.x + pp.y*pp.y;   // pp.pp
        float d3 = pp.x*mc.x + pp.y*mc.y;   // pp.mc
        float d4 = pp.x*xv.x + pp.y*xv.y;   // pp.x
        float d5 = mc.x*xv.x + mc.y*xv.y;   // mc.x
#pragma unroll
        for (int o = 16; o; o >>= 1) {
            d0 += __shfl_xor_sync(0xffffffffu, d0, o);
            d1 += __shfl_xor_sync(0xffffffffu, d1, o);
            d2 += __shfl_xor_sync(0xffffffffu, d2, o);
            d3 += __shfl_xor_sync(0xffffffffu, d3, o);
            d4 += __shfl_xor_sync(0xffffffffu, d4, o);
            d5 += __shfl_xor_sync(0xffffffffu, d5, o);
        }
        float mc63 = __shfl_sync(0xffffffffu, mc.y, 31);
        float pp63 = __shfl_sync(0xffffffffu, pp.y, 31);

        // scalar chain (all lanes redundant)
        float cn = fmaxf(sqrtf(d0), 1e-15f);
        float f  = (cn > 0.996f) ? (0.996f / cn) : 1.0f;
        f *= SCALING_F;                      // zc = f * x   (zc[63] = 0)
        float mn2 = fmaxf(d1, 1e-15f);
        float im  = 1.0f / mn2;              // a = im * mc
        float a2  = d1 * im * im;
        float r2  = a2 - 1.0f;
        float un2 = fmaxf(d2 - 2.0f*d3*im + a2, 1e-15f);
        float s1  = r2 / un2;
        float t1  = 1.0f - s1;               // zp = s1*pp + t1*a
        float zpn2 = s1*s1*d2 + 2.0f*s1*t1*d3*im + t1*t1*a2;
        float pn  = fmaxf(sqrtf(zpn2), 1e-15f);
        float zpzc = f * (s1*d4 + t1*d5*im);
        float zp63 = s1*pp63 + t1*mc63*im;
        float num = -zpzc / pn;              // q.zc = zc[63] = 0
        float den = 2.0f - 2.0f*zp63/pn;
        float m   = num / den;
        float g   = 2.0f*m/pn;               // zcc = zc + g*zp - 2m*e63
        float zcc2 = f*f*d0 + g*g*zpn2 + 4.0f*m*m + 2.0f*g*zpzc - 4.0f*m*g*zp63;
        float zca  = f*d5*im;
        float zpa  = s1*d3*im + t1*a2;
        float zcca = zca + g*zpa - 2.0f*m*mc63*im;
        float u2n  = fmaxf(zcc2 - 2.0f*zcca + a2, 1e-15f);
        float s2   = r2 / u2n;
        float t2   = 1.0f - s2;              // zn = s2*zcc + t2*a
        float cx = s2*f;
        float cp = s2*g*s1;
        float cm = (s2*g*t1 + t2)*im;
        float ce = -2.0f*m*s2;

        float2 zn;
        zn.x = cx*xv.x + cp*pp.x + cm*mc.x;
        zn.y = cx*xv.y + cp*pp.y + cm*mc.y;
        if (lane == 31) zn.y += ce;
        zn2[off] = zn;

        if (last) {
            float znn2 = s2*s2*zcc2 + 2.0f*s2*t2*zcca + t2*t2*a2;
            float yn = fmaxf(sqrtf(fmaxf(znn2, 0.f)), 1e-15f);
            float tt = fminf(yn, 1.0f);
            float sc = atanhf(tt) / yn;
            int bg = __ldg(&batch[gr]);
            red_add_v2(&g_pool[bg * 64 + lane * 2], zn.x * sc, zn.y * sc);
        }
    }
}

// ---------------- head MLP + log_softmax ----------------
__global__ void k_head(const float* __restrict__ fc1W, const float* __restrict__ fc1b,
                       const float* __restrict__ fc2W, const float* __restrict__ fc2b,
                       const float* __restrict__ fc3W, const float* __restrict__ fc3b,
                       float* __restrict__ out) {
    __shared__ float sp[64], h1[128], h2[64], lo[10];
    int g = blockIdx.x;
    int t = threadIdx.x;
    if (t < 64) sp[t] = g_pool[g * 64 + t];
    __syncthreads();
    {
        float acc = fc1b[t];
#pragma unroll 8
        for (int k = 0; k < 64; k++) acc = fmaf(sp[k], fc1W[k * 128 + t], acc);
        h1[t] = fmaxf(acc, 0.f);
    }
    __syncthreads();
    if (t < 64) {
        float acc = fc2b[t];
#pragma unroll 8
        for (int k = 0; k < 128; k++) acc = fmaf(h1[k], fc2W[k * 64 + t], acc);
        h2[t] = fmaxf(acc, 0.f);
    }
    __syncthreads();
    if (t < 10) {
        float acc = fc3b[t];
#pragma unroll 8
        for (int k = 0; k < 64; k++) acc = fmaf(h2[k], fc3W[k * 10 + t], acc);
        lo[t] = acc;
    }
    __syncthreads();
    if (t == 0) {
        float mx = lo[0];
#pragma unroll
        for (int c = 1; c < 10; c++) mx = fmaxf(mx, lo[c]);
        float s = 0.f;
#pragma unroll
        for (int c = 0; c < 10; c++) s += expf(lo[c] - mx);
        float lse = mx + logf(s);
#pragma unroll
        for (int c = 0; c < 10; c++) out[g * 10 + c] = lo[c] - lse;
    }
}

// ---------------- launch ----------------
extern "C" void kernel_launch(void* const* d_in, const int* in_sizes, int n_in,
                              void* d_out, int out_size) {
    const float* x     = (const float*)d_in[0];
    const int*   ei    = (const int*)d_in[1];
    const int*   batch = (const int*)d_in[2];
    const float* W0    = (const float*)d_in[3];
    const float* b0    = (const float*)d_in[4];
    const float* cW1   = (const float*)d_in[5];
    const float* cb1   = (const float*)d_in[6];
    const float* gamma = (const float*)d_in[7];
    const float* beta  = (const float*)d_in[8];
    const float* cW2   = (const float*)d_in[9];
    const float* cb2   = (const float*)d_in[10];
    const float* fc1W  = (const float*)d_in[11];
    const float* fc1b  = (const float*)d_in[12];
    const float* fc2W  = (const float*)d_in[13];
    const float* fc2b  = (const float*)d_in[14];
    const float* fc3W  = (const float*)d_in[15];
    const float* fc3b  = (const float*)d_in[16];
    float* out = (float*)d_out;

    const int gemmGrid = (NN + TR - 1) / TR;     // 391
    const int edgeGrid = (EE * 16) / 256;        // 50000

    k_gemm0<<<gemmGrid, 256>>>(x, W0, b0);
    for (int l = 0; l < 3; l++) {
        k_edge<<<edgeGrid, 256>>>(ei);
        k_gemmA<<<gemmGrid, 256>>>(cW1 + l * 64 * 64, cb1 + l * 64);
        k_gemmB<<<gemmGrid, 256>>>(cW2 + l * 64 * 64, cb2 + l * 64,
                                   gamma + l * 64, beta + l * 64,
                                   batch, l, (l == 2) ? 1 : 0);
    }
    k_head<<<512, 128>>>(fc1W, fc1b, fc2W, fc2b, fc3W, fc3b, out);
}

// round 10
// speedup vs baseline: 1.9077x; 1.0847x over previous
#include <cuda_runtime.h>
#include <cuda_bf16.h>
#include <stdint.h>
#include <math.h>

#define NN 50000
#define EE 800000
#define DIN 128
#define DD 64
#define GG 512
#define TR 128
#define SCALING_F 0.46211715726000974f

// ---------------- scratch ----------------
__device__ __align__(16) float g_x[NN * DD];
__device__ __align__(16) float g_h[NN * DD];
__device__ __align__(16) float g_agg[NN * DD];
__device__ __align__(16) float g_Z[3][NN * DD];
__device__ __align__(16) float g_stats[2 * DD];
__device__ __align__(16) float g_pool[GG * DD];

__device__ __forceinline__ void red_add_v2(float* p, float a, float b) {
    asm volatile("red.global.add.v2.f32 [%0], {%1, %2};"
                 :: "l"(p), "f"(a), "f"(b) : "memory");
}
__device__ __forceinline__ void red_add_v4(float* p, float4 v) {
    asm volatile("red.global.add.v4.f32 [%0], {%1, %2, %3, %4};"
                 :: "l"(p), "f"(v.x), "f"(v.y), "f"(v.z), "f"(v.w) : "memory");
}

// split bf16: h = bf16(f), l = bf16(f - h); packed as bf16x2
__device__ __forceinline__ void pack2(float f0, float f1, uint32_t& h, uint32_t& l) {
    __nv_bfloat162 hb;
    hb.x = __float2bfloat16_rn(f0);
    hb.y = __float2bfloat16_rn(f1);
    __nv_bfloat162 lb;
    lb.x = __float2bfloat16_rn(f0 - __bfloat162float(hb.x));
    lb.y = __float2bfloat16_rn(f1 - __bfloat162float(hb.y));
    h = *reinterpret_cast<uint32_t*>(&hb);
    l = *reinterpret_cast<uint32_t*>(&lb);
}

__device__ __forceinline__ void mma_bf16(float* d, uint32_t a0, uint32_t a1,
                                         uint32_t a2, uint32_t a3,
                                         uint32_t b0, uint32_t b1) {
    asm volatile("mma.sync.aligned.m16n8k16.row.col.f32.bf16.bf16.f32 "
                 "{%0,%1,%2,%3}, {%4,%5,%6,%7}, {%8,%9}, {%0,%1,%2,%3};"
                 : "+f"(d[0]), "+f"(d[1]), "+f"(d[2]), "+f"(d[3])
                 : "r"(a0), "r"(a1), "r"(a2), "r"(a3), "r"(b0), "r"(b1));
}

// As layout: [wt(8)][kstep(4)][lane(32)][8 u32] = 8192 u32 (32KB)
// slot per lane: a0h,a1h,a2h,a3h, a0l,a1l,a2l,a3l
__device__ __forceinline__ void pack_A(uint32_t* As, int r, int cq, float4 v) {
    int wt = r >> 4;
    int ri = r & 15;
    int k0 = cq * 4;
    int ks = k0 >> 4;
    int ki = k0 & 15;                       // 0,4,8,12
    int reg = (ri >> 3) + ((ki >> 3) << 1); // a0/a1/a2/a3
    int lane0 = ((ri & 7) << 2) | ((ki >> 1) & 3);
    uint32_t h0, l0, h1, l1;
    pack2(v.x, v.y, h0, l0);
    pack2(v.z, v.w, h1, l1);
    uint32_t* p0 = As + ((wt * 4 + ks) * 32 + lane0) * 8 + reg;
    p0[0] = h0;
    p0[4] = l0;
    p0[8] = h1;                              // lane0+1
    p0[12] = l1;
}

// Wsp layout: [kstep(4)][nt(8)][lane(32)][4 u32] = 4096 u32 (16KB)
// slot: b0h, b1h, b0l, b1l
__device__ __forceinline__ void pack_W(uint32_t* Wsp, int k2, int n, float w0, float w1) {
    int ks = k2 >> 3;
    int p = k2 & 7;
    int tid4 = p & 3;
    int bsel = p >> 2;
    int lane = ((n & 7) << 2) | tid4;
    int nt = n >> 3;
    uint32_t h, l;
    pack2(w0, w1, h, l);
    uint32_t* q = Wsp + ((ks * 8 + nt) * 32 + lane) * 4;
    q[bsel] = h;
    q[2 + bsel] = l;
}

// d[8][4] += A(16x64) * W(64x64), 3-term split-bf16
__device__ __forceinline__ void mma_main(const uint32_t* As, const uint32_t* Wsp,
                                         int wid, int lane, float d[8][4]) {
#pragma unroll
    for (int ks = 0; ks < 4; ks++) {
        const uint32_t* ap = As + ((wid * 4 + ks) * 32 + lane) * 8;
        uint4 AH = *(const uint4*)ap;
        uint4 AL = *(const uint4*)(ap + 4);
        const uint32_t* wp = Wsp + (ks * 256 + lane) * 4;
#pragma unroll
        for (int nt = 0; nt < 8; nt++) {
            uint4 B = *(const uint4*)(wp + nt * 128);
            mma_bf16(d[nt], AH.x, AH.y, AH.z, AH.w, B.x, B.y);
            mma_bf16(d[nt], AH.x, AH.y, AH.z, AH.w, B.z, B.w);
            mma_bf16(d[nt], AL.x, AL.y, AL.z, AL.w, B.x, B.y);
        }
    }
}

// accumulators -> tile[128][64] f32 (tile aliases As; warp writes only its own slice)
__device__ __forceinline__ void mma_scatter(float* tile, int wid, int lane, float d[8][4]) {
    int g = lane >> 2;
    int tq = lane & 3;
    int r0 = wid * 16 + g;
#pragma unroll
    for (int nt = 0; nt < 8; nt++) {
        int c = nt * 8 + tq * 2;
        *(float2*)&tile[r0 * 64 + c] = make_float2(d[nt][0], d[nt][1]);
        *(float2*)&tile[(r0 + 8) * 64 + c] = make_float2(d[nt][2], d[nt][3]);
    }
}

// ---------------- GEMM 0 ----------------
__global__ __launch_bounds__(256, 3) void k_gemm0(const float* __restrict__ xin,
                                                  const float* __restrict__ W0,
                                                  const float* __restrict__ b0) {
    __shared__ __align__(16) uint32_t As[8192];
    __shared__ __align__(16) uint32_t Wsp[4096];
    float* tile = (float*)As;
    int t = threadIdx.x;
    int lane = t & 31;
    int wid = t >> 5;
    int R0 = blockIdx.x * TR;
    float4 z4 = make_float4(0.f, 0.f, 0.f, 0.f);

    if (blockIdx.x < 32) ((float4*)g_pool)[blockIdx.x * 256u + t] = z4;
    if (blockIdx.x == 0 && t < 128) g_stats[t] = 0.f;

    float d[8][4] = {};
    for (int kb = 0; kb < 128; kb += 64) {
        if (kb) __syncthreads();
#pragma unroll
        for (int i = 0; i < 8; i++) {
            int idx4 = t + i * 256;
            int r = idx4 >> 4;
            int cq = idx4 & 15;
            int gr = R0 + r;
            float4 v = (gr < NN) ? *(const float4*)&xin[gr * 128 + kb + cq * 4] : z4;
            pack_A(As, r, cq, v);
        }
#pragma unroll
        for (int i = 0; i < 8; i++) {
            int pidx = t + i * 256;
            int k2 = pidx >> 6;
            int n = pidx & 63;
            int gk = kb + 2 * k2;
            pack_W(Wsp, k2, n, W0[gk * 64 + n], W0[(gk + 1) * 64 + n]);
        }
        __syncthreads();
        mma_main(As, Wsp, wid, lane, d);
    }
    mma_scatter(tile, wid, lane, d);
    __syncthreads();

    int tx = t & 15;
    int ty = t >> 4;
    int c4 = tx * 4;
    float4 bb = *(const float4*)&b0[c4];
    float o[8][4];
    float pr[8];
#pragma unroll
    for (int r = 0; r < 8; r++) {
        float4 dv = *(const float4*)&tile[(ty * 8 + r) * 64 + c4];
        o[r][0] = fmaxf(dv.x + bb.x, 0.f);
        o[r][1] = fmaxf(dv.y + bb.y, 0.f);
        o[r][2] = fmaxf(dv.z + bb.z, 0.f);
        o[r][3] = fmaxf(dv.w + bb.w, 0.f);
        pr[r] = o[r][0]*o[r][0] + o[r][1]*o[r][1] + o[r][2]*o[r][2] + o[r][3]*o[r][3];
    }
#pragma unroll
    for (int m = 1; m < 16; m <<= 1) {
#pragma unroll
        for (int r = 0; r < 8; r++) pr[r] += __shfl_xor_sync(0xffffffffu, pr[r], m);
    }
#pragma unroll
    for (int r = 0; r < 8; r++) {
        int gr = R0 + ty * 8 + r;
        if (gr < NN) {
            float4 ov = make_float4(o[r][0], o[r][1], o[r][2], o[r][3]);
            *(float4*)&g_x[gr * 64 + c4] = ov;
            *(float4*)&g_agg[gr * 64 + c4] = ov;
            float cn = fmaxf(sqrtf(pr[r]), 1e-15f);
            float f = (cn > 0.996f) ? (0.996f / cn) : 1.0f;
            f *= SCALING_F;
            *(float4*)&g_Z[0][gr * 64 + c4] =
                make_float4(o[r][0]*f, o[r][1]*f, o[r][2]*f, o[r][3]*f);
        }
    }
}

// ---------------- edge scatter ----------------
__global__ void k_edge(const int* __restrict__ ei) {
    unsigned tid = blockIdx.x * 256u + threadIdx.x;
    if (blockIdx.x == 0 && threadIdx.x < 128) g_stats[threadIdx.x] = 0.f;
    unsigned e = tid >> 4;
    unsigned q = tid & 15u;
    int s = __ldg(&ei[e]);
    int dn = __ldg(&ei[EE + e]);
    float4 v = *(const float4*)&g_x[(unsigned)s * 64u + q * 4u];
    red_add_v4(&g_agg[(unsigned)dn * 64u + q * 4u], v);
}

// ---------------- GEMM A (stats buffers alias Wsp after mma) ----------------
__global__ __launch_bounds__(256, 3) void k_gemmA(const float* __restrict__ W,
                                                  const float* __restrict__ b) {
    __shared__ __align__(16) uint32_t As[8192];
    __shared__ __align__(16) uint32_t Wsp[4096];
    float* tile = (float*)As;
    float* s_sum = (float*)Wsp;        // reused after mma_main
    float* s_sq = (float*)Wsp + 64;
    int t = threadIdx.x;
    int lane = t & 31;
    int wid = t >> 5;
    int R0 = blockIdx.x * TR;
    float4 z4 = make_float4(0.f, 0.f, 0.f, 0.f);

#pragma unroll
    for (int i = 0; i < 8; i++) {
        int idx4 = t + i * 256;
        int r = idx4 >> 4;
        int cq = idx4 & 15;
        int gr = R0 + r;
        float4 v = (gr < NN) ? *(const float4*)&g_agg[gr * 64 + cq * 4] : z4;
        pack_A(As, r, cq, v);
    }
#pragma unroll
    for (int i = 0; i < 8; i++) {
        int pidx = t + i * 256;
        int k2 = pidx >> 6;
        int n = pidx & 63;
        pack_W(Wsp, k2, n, W[2 * k2 * 64 + n], W[(2 * k2 + 1) * 64 + n]);
    }
    __syncthreads();
    float d[8][4] = {};
    mma_main(As, Wsp, wid, lane, d);
    mma_scatter(tile, wid, lane, d);
    __syncthreads();                   // everyone done with Wsp + tile ready
    if (t < 64) { s_sum[t] = 0.f; s_sq[t] = 0.f; }
    __syncthreads();

    int tx = t & 15;
    int ty = t >> 4;
    int c4 = tx * 4;
    float4 bb = *(const float4*)&b[c4];
    float ps[4] = {0.f, 0.f, 0.f, 0.f};
    float pq[4] = {0.f, 0.f, 0.f, 0.f};
#pragma unroll
    for (int i = 0; i < 8; i++) {
        int gr = R0 + ty * 8 + i;
        float4 dv = *(const float4*)&tile[(ty * 8 + i) * 64 + c4];
        float o0 = fmaxf(dv.x + bb.x, 0.f);
        float o1 = fmaxf(dv.y + bb.y, 0.f);
        float o2 = fmaxf(dv.z + bb.z, 0.f);
        float o3 = fmaxf(dv.w + bb.w, 0.f);
        if (gr < NN) {
            *(float4*)&g_h[gr * 64 + c4] = make_float4(o0, o1, o2, o3);
            ps[0] += o0; ps[1] += o1; ps[2] += o2; ps[3] += o3;
            pq[0] += o0*o0; pq[1] += o1*o1; pq[2] += o2*o2; pq[3] += o3*o3;
        }
    }
#pragma unroll
    for (int j = 0; j < 4; j++) {
        atomicAdd(&s_sum[c4 + j], ps[j]);
        atomicAdd(&s_sq[c4 + j], pq[j]);
    }
    __syncthreads();
    if (t < 64) {
        atomicAdd(&g_stats[t], s_sum[t]);
        atomicAdd(&g_stats[64 + t], s_sq[t]);
    }
}

// ---------------- GEMM B + hyperbolic update (BN affine in registers) ----------------
__global__ __launch_bounds__(256, 3) void k_gemmB(const float* __restrict__ W,
                                                  const float* __restrict__ b,
                                                  const float* __restrict__ gamma,
                                                  const float* __restrict__ beta,
                                                  const int* __restrict__ batch,
                                                  int iter, int last) {
    __shared__ __align__(16) uint32_t As[8192];
    __shared__ __align__(16) uint32_t Wsp[4096];
    float* tile = (float*)As;
    int t = threadIdx.x;
    int lane = t & 31;
    int wid = t >> 5;
    int R0 = blockIdx.x * TR;
    int tx = t & 15;
    int ty = t >> 4;
    int c4 = tx * 4;

    // BN affine for this thread's fixed column quad (cq == tx in all pack iterations)
    float scr[4], shr[4];
#pragma unroll
    for (int j = 0; j < 4; j++) {
        int c = c4 + j;
        float mean = g_stats[c] * (1.0f / NN);
        float var = g_stats[64 + c] * (1.0f / NN) - mean * mean;
        float inv = rsqrtf(var + 1e-5f);
        float s = gamma[c] * inv;
        scr[j] = s;
        shr[j] = beta[c] - mean * s;
    }

#pragma unroll
    for (int i = 0; i < 8; i++) {
        int idx4 = t + i * 256;
        int r = idx4 >> 4;
        int cq = idx4 & 15;          // == tx
        int gr = R0 + r;
        float4 v;
        if (gr < NN) {
            float4 h = *(const float4*)&g_h[gr * 64 + cq * 4];
            v.x = fmaf(h.x, scr[0], shr[0]);
            v.y = fmaf(h.y, scr[1], shr[1]);
            v.z = fmaf(h.z, scr[2], shr[2]);
            v.w = fmaf(h.w, scr[3], shr[3]);
        } else {
            v = make_float4(0.f, 0.f, 0.f, 0.f);
        }
        pack_A(As, r, cq, v);
    }
#pragma unroll
    for (int i = 0; i < 8; i++) {
        int pidx = t + i * 256;
        int k2 = pidx >> 6;
        int n = pidx & 63;
        pack_W(Wsp, k2, n, W[2 * k2 * 64 + n], W[(2 * k2 + 1) * 64 + n]);
    }
    __syncthreads();
    float d[8][4] = {};
    mma_main(As, Wsp, wid, lane, d);
    mma_scatter(tile, wid, lane, d);
    __syncthreads();

    float4 bb = *(const float4*)&b[c4];
#pragma unroll
    for (int i = 0; i < 8; i++) {
        int r = ty * 8 + i;
        int gr = R0 + r;
        float4 dv = *(const float4*)&tile[r * 64 + c4];
        float4 ov;
        ov.x = fmaxf(dv.x + bb.x, 0.f);
        ov.y = fmaxf(dv.y + bb.y, 0.f);
        ov.z = fmaxf(dv.z + bb.z, 0.f);
        ov.w = fmaxf(dv.w + bb.w, 0.f);
        if (c4 == 60) ov.w = 0.f;    // x[:, -1] = 0
        *(float4*)&tile[r * 64 + c4] = ov;
        if (gr < NN) {
            *(float4*)&g_x[gr * 64 + c4] = ov;
            *(float4*)&g_agg[gr * 64 + c4] = ov;
        }
    }
    __syncthreads();

    // hyperbolic update, closed form: zn = cx*x + cpp*pp + cmm*mc + ce*e63
    const float2* zc2 = (const float2*)g_Z[iter];
    const float2* zp2 = (const float2*)g_Z[(iter + 2) % 3];
    float2* zn2 = (float2*)g_Z[(iter + 1) % 3];

    for (int i = 0; i < 16; i++) {
        int rr = wid * 16 + i;
        int gr = R0 + rr;
        if (gr >= NN) break;
        int off = gr * 32 + lane;
        float2 xv = *(const float2*)&tile[rr * 64 + lane * 2];
        float2 mc = zc2[off];
        float2 pp = (iter == 0) ? make_float2(0.f, 0.f) : zp2[off];

        float d0 = xv.x*xv.x + xv.y*xv.y;
        float d1 = mc.x*mc.x + mc.y*mc.y;
        float d2 = pp.x*pp.x + pp.y*pp.y;
        float d3 = pp.x*mc.x + pp.y*mc.y;
        float d4 = pp.x*xv.x + pp.y*xv.y;
        float d5 = mc.x*xv.x + mc.y*xv.y;
#pragma unroll
        for (int o = 16; o; o >>= 1) {
            d0 += __shfl_xor_sync(0xffffffffu, d0, o);
            d1 += __shfl_xor_sync(0xffffffffu, d1, o);
            d2 += __shfl_xor_sync(0xffffffffu, d2, o);
            d3 += __shfl_xor_sync(0xffffffffu, d3, o);
            d4 += __shfl_xor_sync(0xffffffffu, d4, o);
            d5 += __shfl_xor_sync(0xffffffffu, d5, o);
        }
        float mc63 = __shfl_sync(0xffffffffu, mc.y, 31);
        float pp63 = __shfl_sync(0xffffffffu, pp.y, 31);

        float cn = fmaxf(sqrtf(d0), 1e-15f);
        float f = (cn > 0.996f) ? (0.996f / cn) : 1.0f;
        f *= SCALING_F;
        float mn2 = fmaxf(d1, 1e-15f);
        float im = 1.0f / mn2;
        float a2 = d1 * im * im;
        float r2 = a2 - 1.0f;
        float un2 = fmaxf(d2 - 2.0f*d3*im + a2, 1e-15f);
        float s1 = r2 / un2;
        float t1 = 1.0f - s1;
        float zpn2 = s1*s1*d2 + 2.0f*s1*t1*d3*im + t1*t1*a2;
        float pn = fmaxf(sqrtf(zpn2), 1e-15f);
        float zpzc = f * (s1*d4 + t1*d5*im);
        float zp63 = s1*pp63 + t1*mc63*im;
        float mnum = -zpzc / pn;
        float mden = 2.0f - 2.0f*zp63/pn;
        float mm = mnum / mden;
        float gg = 2.0f*mm/pn;
        float zcc2 = f*f*d0 + gg*gg*zpn2 + 4.0f*mm*mm + 2.0f*gg*zpzc - 4.0f*mm*gg*zp63;
        float zca = f*d5*im;
        float zpa = s1*d3*im + t1*a2;
        float zcca = zca + gg*zpa - 2.0f*mm*mc63*im;
        float u2n = fmaxf(zcc2 - 2.0f*zcca + a2, 1e-15f);
        float s2 = r2 / u2n;
        float t2 = 1.0f - s2;
        float cx = s2*f;
        float cpp = s2*gg*s1;
        float cmm = (s2*gg*t1 + t2)*im;
        float ce = -2.0f*mm*s2;

        float znx = cx*xv.x + cpp*pp.x + cmm*mc.x;
        float zny = cx*xv.y + cpp*pp.y + cmm*mc.y;
        if (lane == 31) zny += ce;
        zn2[off] = make_float2(znx, zny);

        if (last) {
            float znn2 = s2*s2*zcc2 + 2.0f*s2*t2*zcca + t2*t2*a2;
            float yn = fmaxf(sqrtf(fmaxf(znn2, 0.f)), 1e-15f);
            float tt = fminf(yn, 1.0f);
            float sc = atanhf(tt) / yn;
            int bg = __ldg(&batch[gr]);
            red_add_v2(&g_pool[bg * 64 + lane * 2], znx * sc, zny * sc);
        }
    }
}

// ---------------- head MLP + log_softmax ----------------
__global__ void k_head(const float* __restrict__ fc1W, const float* __restrict__ fc1b,
                       const float* __restrict__ fc2W, const float* __restrict__ fc2b,
                       const float* __restrict__ fc3W, const float* __restrict__ fc3b,
                       float* __restrict__ out) {
    __shared__ float sp[64];
    __shared__ float h1[128];
    __shared__ float h2[64];
    __shared__ float lo[10];
    int g = blockIdx.x;
    int t = threadIdx.x;
    if (t < 64) sp[t] = g_pool[g * 64 + t];
    __syncthreads();
    {
        float acc = fc1b[t];
#pragma unroll 8
        for (int k = 0; k < 64; k++) acc = fmaf(sp[k], fc1W[k * 128 + t], acc);
        h1[t] = fmaxf(acc, 0.f);
    }
    __syncthreads();
    if (t < 64) {
        float acc = fc2b[t];
#pragma unroll 8
        for (int k = 0; k < 128; k++) acc = fmaf(h1[k], fc2W[k * 64 + t], acc);
        h2[t] = fmaxf(acc, 0.f);
    }
    __syncthreads();
    if (t < 10) {
        float acc = fc3b[t];
#pragma unroll 8
        for (int k = 0; k < 64; k++) acc = fmaf(h2[k], fc3W[k * 10 + t], acc);
        lo[t] = acc;
    }
    __syncthreads();
    if (t == 0) {
        float mx = lo[0];
#pragma unroll
        for (int c = 1; c < 10; c++) mx = fmaxf(mx, lo[c]);
        float s = 0.f;
#pragma unroll
        for (int c = 0; c < 10; c++) s += expf(lo[c] - mx);
        float lse = mx + logf(s);
#pragma unroll
        for (int c = 0; c < 10; c++) out[g * 10 + c] = lo[c] - lse;
    }
}

// ---------------- launch ----------------
extern "C" void kernel_launch(void* const* d_in, const int* in_sizes, int n_in,
                              void* d_out, int out_size) {
    const float* x     = (const float*)d_in[0];
    const int*   ei    = (const int*)d_in[1];
    const int*   batch = (const int*)d_in[2];
    const float* W0    = (const float*)d_in[3];
    const float* b0    = (const float*)d_in[4];
    const float* cW1   = (const float*)d_in[5];
    const float* cb1   = (const float*)d_in[6];
    const float* gamma = (const float*)d_in[7];
    const float* beta  = (const float*)d_in[8];
    const float* cW2   = (const float*)d_in[9];
    const float* cb2   = (const float*)d_in[10];
    const float* fc1W  = (const float*)d_in[11];
    const float* fc1b  = (const float*)d_in[12];
    const float* fc2W  = (const float*)d_in[13];
    const float* fc2b  = (const float*)d_in[14];
    const float* fc3W  = (const float*)d_in[15];
    const float* fc3b  = (const float*)d_in[16];
    float* out = (float*)d_out;

    const int gemmGrid = (NN + TR - 1) / TR;     // 391
    const int edgeGrid = (EE * 16) / 256;        // 50000

    k_gemm0<<<gemmGrid, 256>>>(x, W0, b0);
    for (int l = 0; l < 3; l++) {
        k_edge<<<edgeGrid, 256>>>(ei);
        k_gemmA<<<gemmGrid, 256>>>(cW1 + l * 64 * 64, cb1 + l * 64);
        k_gemmB<<<gemmGrid, 256>>>(cW2 + l * 64 * 64, cb2 + l * 64,
                                   gamma + l * 64, beta + l * 64,
                                   batch, l, (l == 2) ? 1 : 0);
    }
    k_head<<<512, 128>>>(fc1W, fc1b, fc2W, fc2b, fc3W, fc3b, out);
}